// round 1
// baseline (speedup 1.0000x reference)
#include <cuda_runtime.h>

#define NN 100000
#define NE 600000
#define ZF 128

// Scratch (allocation-free rule: __device__ globals)
__device__ float g_Ps[(size_t)NN * ZF];   // node_features @ We1[0:128]
__device__ float g_Pr[(size_t)NN * ZF];   // node_features @ We1[128:256]
__device__ float g_agg[(size_t)NN * ZF];  // segment_sum(e_upd, receivers)

// ---------------------------------------------------------------------------
// 32x128x128 GEMM tile: 256 threads, per-thread 4 rows x 4 cols.
// As: smem [32][128] row-major. W: global [128][128] row-major (K-major rows).
// Within a warp all lanes share ty -> As reads are broadcasts (conflict-free).
// W reads are 512B-contiguous per warp (coalesced LDG.128, L1/L2-hot).
// ---------------------------------------------------------------------------
__device__ __forceinline__ void gemm32(const float* As,
                                       const float* __restrict__ W,
                                       int tx, int ty, float acc[4][4])
{
#pragma unroll 1
    for (int k = 0; k < 128; k += 4) {
        float b4[4][4];
#pragma unroll
        for (int kk = 0; kk < 4; kk++)
            *(float4*)(b4[kk]) = __ldg((const float4*)(W + (k + kk) * 128 + tx * 4));
#pragma unroll
        for (int i = 0; i < 4; i++) {
            float a4[4];
            *(float4*)(a4) = *(const float4*)(As + (ty * 4 + i) * 128 + k);
#pragma unroll
            for (int kk = 0; kk < 4; kk++)
#pragma unroll
                for (int j = 0; j < 4; j++)
                    acc[i][j] += a4[kk] * b4[kk][j];
        }
    }
}

// ---------------------------------------------------------------------------
// proj: P_s = X @ We1[0:128], P_r = X @ We1[128:256]; also zeroes g_agg.
// grid = 3125 (100000/32 exact); each block zeroes its 1024-float4 agg slice.
// ---------------------------------------------------------------------------
__global__ void __launch_bounds__(256, 2)
proj_kernel(const float* __restrict__ X, const float* __restrict__ We1)
{
    __shared__ float As[32 * 128];

    // zero agg slice: 3125 blocks * 1024 float4 = 3,200,000 = NN*ZF/4 exactly
    {
        float4* aggv = (float4*)g_agg;
        int base = blockIdx.x * 1024 + threadIdx.x;
#pragma unroll
        for (int i = 0; i < 4; i++)
            aggv[base + i * 256] = make_float4(0.f, 0.f, 0.f, 0.f);
    }

    const int m0 = blockIdx.x * 32;
    const int tid = threadIdx.x, tx = tid & 31, ty = tid >> 5;

    // stage X tile [32][128]
    {
        const float4* src = (const float4*)X;
        float4* dst = (float4*)As;
#pragma unroll
        for (int i = tid; i < 1024; i += 256)
            dst[i] = src[m0 * 32 + i];
    }
    __syncthreads();

    float acca[4][4] = {}, accb[4][4] = {};
    const float* Wa = We1;              // rows [0,128)
    const float* Wb = We1 + 128 * 128;  // rows [128,256)

#pragma unroll 1
    for (int k = 0; k < 128; k += 4) {
        float ba[4][4], bb[4][4];
#pragma unroll
        for (int kk = 0; kk < 4; kk++) {
            *(float4*)(ba[kk]) = __ldg((const float4*)(Wa + (k + kk) * 128 + tx * 4));
            *(float4*)(bb[kk]) = __ldg((const float4*)(Wb + (k + kk) * 128 + tx * 4));
        }
#pragma unroll
        for (int i = 0; i < 4; i++) {
            float a4[4];
            *(float4*)(a4) = *(const float4*)(As + (ty * 4 + i) * 128 + k);
#pragma unroll
            for (int kk = 0; kk < 4; kk++)
#pragma unroll
                for (int j = 0; j < 4; j++) {
                    acca[i][j] += a4[kk] * ba[kk][j];
                    accb[i][j] += a4[kk] * bb[kk][j];
                }
        }
    }

#pragma unroll
    for (int i = 0; i < 4; i++) {
        int row = m0 + ty * 4 + i;
        float4 va = make_float4(acca[i][0], acca[i][1], acca[i][2], acca[i][3]);
        float4 vb = make_float4(accb[i][0], accb[i][1], accb[i][2], accb[i][3]);
        *(float4*)(g_Ps + (size_t)row * 128 + tx * 4) = va;
        *(float4*)(g_Pr + (size_t)row * 128 + tx * 4) = vb;
    }
}

// ---------------------------------------------------------------------------
// edge: h1 = relu(gather(P_s,s) + gather(P_r,r) + E@We1[256:384] + be1)
//       h2 = relu(h1@We2 + be2);  e_upd = h2@We3 + be3
//       new_edges = e_upd + E;  atomicAdd(agg[recv], e_upd)
// grid = 18750 (600000/32 exact)
// ---------------------------------------------------------------------------
__global__ void __launch_bounds__(256, 2)
edge_kernel(const float* __restrict__ EF,
            const int* __restrict__ senders, const int* __restrict__ receivers,
            const float* __restrict__ We1, const float* __restrict__ be1,
            const float* __restrict__ We2, const float* __restrict__ be2,
            const float* __restrict__ We3, const float* __restrict__ be3,
            float* __restrict__ out_edges)
{
    __shared__ float As[32 * 128];
    __shared__ float h1[32 * 128];
    __shared__ float h2[32 * 128];

    const int m0 = blockIdx.x * 32;
    const int tid = threadIdx.x, tx = tid & 31, ty = tid >> 5;

    // stage edge-feature tile
    {
        const float4* src = (const float4*)EF;
        float4* dst = (float4*)As;
#pragma unroll
        for (int i = tid; i < 1024; i += 256)
            dst[i] = src[m0 * 32 + i];
    }
    __syncthreads();

    // layer 1: E @ We1[256:384] + gathers + bias, relu
    float acc[4][4] = {};
    gemm32(As, We1 + 256 * 128, tx, ty, acc);
    {
        float4 bias = __ldg((const float4*)(be1 + tx * 4));
#pragma unroll
        for (int i = 0; i < 4; i++) {
            int row = ty * 4 + i;
            int e = m0 + row;
            int s = __ldg(senders + e);
            int r = __ldg(receivers + e);
            float4 ps = __ldg((const float4*)(g_Ps + (size_t)s * 128 + tx * 4));
            float4 pr = __ldg((const float4*)(g_Pr + (size_t)r * 128 + tx * 4));
            float4 v;
            v.x = fmaxf(acc[i][0] + ps.x + pr.x + bias.x, 0.f);
            v.y = fmaxf(acc[i][1] + ps.y + pr.y + bias.y, 0.f);
            v.z = fmaxf(acc[i][2] + ps.z + pr.z + bias.z, 0.f);
            v.w = fmaxf(acc[i][3] + ps.w + pr.w + bias.w, 0.f);
            *(float4*)(h1 + row * 128 + tx * 4) = v;
        }
    }
    __syncthreads();

    // layer 2
    float acc2[4][4] = {};
    gemm32(h1, We2, tx, ty, acc2);
    {
        float4 bias = __ldg((const float4*)(be2 + tx * 4));
#pragma unroll
        for (int i = 0; i < 4; i++) {
            int row = ty * 4 + i;
            float4 v;
            v.x = fmaxf(acc2[i][0] + bias.x, 0.f);
            v.y = fmaxf(acc2[i][1] + bias.y, 0.f);
            v.z = fmaxf(acc2[i][2] + bias.z, 0.f);
            v.w = fmaxf(acc2[i][3] + bias.w, 0.f);
            *(float4*)(h2 + row * 128 + tx * 4) = v;
        }
    }
    __syncthreads();

    // layer 3 + residual + scatter-add
    float acc3[4][4] = {};
    gemm32(h2, We3, tx, ty, acc3);
    {
        float4 bias = __ldg((const float4*)(be3 + tx * 4));
#pragma unroll
        for (int i = 0; i < 4; i++) {
            int row = ty * 4 + i;
            int e = m0 + row;
            int r = __ldg(receivers + e);
            float u0 = acc3[i][0] + bias.x;
            float u1 = acc3[i][1] + bias.y;
            float u2 = acc3[i][2] + bias.z;
            float u3 = acc3[i][3] + bias.w;
            float4 ef = *(const float4*)(As + row * 128 + tx * 4);
            float4 o = make_float4(u0 + ef.x, u1 + ef.y, u2 + ef.z, u3 + ef.w);
            *(float4*)(out_edges + (size_t)e * 128 + tx * 4) = o;
            float* ag = g_agg + (size_t)r * 128 + tx * 4;
            atomicAdd(ag + 0, u0);
            atomicAdd(ag + 1, u1);
            atomicAdd(ag + 2, u2);
            atomicAdd(ag + 3, u3);
        }
    }
}

// ---------------------------------------------------------------------------
// node: h1 = relu(X@Wn1[0:128] + agg@Wn1[128:256] + bn1)
//       h2 = relu(h1@Wn2 + bn2);  new_nodes = h2@Wn3 + bn3 + X
// grid = 3125
// ---------------------------------------------------------------------------
__global__ void __launch_bounds__(256, 2)
node_kernel(const float* __restrict__ X,
            const float* __restrict__ Wn1, const float* __restrict__ bn1,
            const float* __restrict__ Wn2, const float* __restrict__ bn2,
            const float* __restrict__ Wn3, const float* __restrict__ bn3,
            float* __restrict__ out_nodes)
{
    __shared__ float As[32 * 128];
    __shared__ float h1[32 * 128];
    __shared__ float h2[32 * 128];

    const int m0 = blockIdx.x * 32;
    const int tid = threadIdx.x, tx = tid & 31, ty = tid >> 5;

    // stage X tile, K-pass 1
    {
        const float4* src = (const float4*)X;
        float4* dst = (float4*)As;
#pragma unroll
        for (int i = tid; i < 1024; i += 256)
            dst[i] = src[m0 * 32 + i];
    }
    __syncthreads();

    float acc[4][4] = {};
    gemm32(As, Wn1, tx, ty, acc);           // X part (Wn1 rows [0,128))
    __syncthreads();                         // all reads of As done

    // stage agg tile, K-pass 2
    {
        const float4* src = (const float4*)g_agg;
        float4* dst = (float4*)As;
#pragma unroll
        for (int i = tid; i < 1024; i += 256)
            dst[i] = src[m0 * 32 + i];
    }
    __syncthreads();
    gemm32(As, Wn1 + 128 * 128, tx, ty, acc);  // agg part (rows [128,256))

    {
        float4 bias = __ldg((const float4*)(bn1 + tx * 4));
#pragma unroll
        for (int i = 0; i < 4; i++) {
            int row = ty * 4 + i;
            float4 v;
            v.x = fmaxf(acc[i][0] + bias.x, 0.f);
            v.y = fmaxf(acc[i][1] + bias.y, 0.f);
            v.z = fmaxf(acc[i][2] + bias.z, 0.f);
            v.w = fmaxf(acc[i][3] + bias.w, 0.f);
            *(float4*)(h1 + row * 128 + tx * 4) = v;
        }
    }
    __syncthreads();

    float acc2[4][4] = {};
    gemm32(h1, Wn2, tx, ty, acc2);
    {
        float4 bias = __ldg((const float4*)(bn2 + tx * 4));
#pragma unroll
        for (int i = 0; i < 4; i++) {
            int row = ty * 4 + i;
            float4 v;
            v.x = fmaxf(acc2[i][0] + bias.x, 0.f);
            v.y = fmaxf(acc2[i][1] + bias.y, 0.f);
            v.z = fmaxf(acc2[i][2] + bias.z, 0.f);
            v.w = fmaxf(acc2[i][3] + bias.w, 0.f);
            *(float4*)(h2 + row * 128 + tx * 4) = v;
        }
    }
    __syncthreads();

    float acc3[4][4] = {};
    gemm32(h2, Wn3, tx, ty, acc3);
    {
        float4 bias = __ldg((const float4*)(bn3 + tx * 4));
#pragma unroll
        for (int i = 0; i < 4; i++) {
            int row = ty * 4 + i;
            int n = m0 + row;
            float4 xv = __ldg((const float4*)(X + (size_t)n * 128 + tx * 4));
            float4 o;
            o.x = acc3[i][0] + bias.x + xv.x;
            o.y = acc3[i][1] + bias.y + xv.y;
            o.z = acc3[i][2] + bias.z + xv.z;
            o.w = acc3[i][3] + bias.w + xv.w;
            *(float4*)(out_nodes + (size_t)n * 128 + tx * 4) = o;
        }
    }
}

// ---------------------------------------------------------------------------
extern "C" void kernel_launch(void* const* d_in, const int* in_sizes, int n_in,
                              void* d_out, int out_size)
{
    const float* node_features = (const float*)d_in[0];
    const float* edge_features = (const float*)d_in[1];
    const int*   senders       = (const int*)d_in[2];
    const int*   receivers     = (const int*)d_in[3];
    const float* We1 = (const float*)d_in[4];
    const float* be1 = (const float*)d_in[5];
    const float* We2 = (const float*)d_in[6];
    const float* be2 = (const float*)d_in[7];
    const float* We3 = (const float*)d_in[8];
    const float* be3 = (const float*)d_in[9];
    const float* Wn1 = (const float*)d_in[10];
    const float* bn1 = (const float*)d_in[11];
    const float* Wn2 = (const float*)d_in[12];
    const float* bn2 = (const float*)d_in[13];
    const float* Wn3 = (const float*)d_in[14];
    const float* bn3 = (const float*)d_in[15];

    float* out_nodes = (float*)d_out;                    // [NN, 128]
    float* out_edges = (float*)d_out + (size_t)NN * ZF;  // [NE, 128]

    proj_kernel<<<3125, 256>>>(node_features, We1);
    edge_kernel<<<18750, 256>>>(edge_features, senders, receivers,
                                We1, be1, We2, be2, We3, be3, out_edges);
    node_kernel<<<3125, 256>>>(node_features, Wn1, bn1, Wn2, bn2, Wn3, bn3,
                               out_nodes);
}

// round 3
// speedup vs baseline: 1.6208x; 1.6208x over previous
#include <cuda_runtime.h>
#include <cstdint>

#define NN 100000
#define NE 600000

// ---------------- device scratch (allocation-free rule) ----------------
__device__ float g_Ps[(size_t)NN * 128];      // X @ We1[0:128]
__device__ float g_Pr[(size_t)NN * 128];      // X @ We1[128:256]
__device__ float g_agg[(size_t)NN * 128];     // segment_sum(e_upd, receivers)
__device__ uint32_t g_wimg[9][16384];         // pre-permuted tf32 weight images [n][k]

// ---------------- helpers ----------------
__device__ __forceinline__ uint32_t f2tf(float x) {
    uint32_t r;
    asm("cvt.rna.tf32.f32 %0, %1;" : "=r"(r) : "f"(x));
    return r;
}

// mma.sync m16n8k8 tf32 (sm_80+, compiles on base sm_100)
__device__ __forceinline__ void mma8(float* d, uint32_t a0, uint32_t a1,
                                     uint32_t a2, uint32_t a3,
                                     uint32_t b0, uint32_t b1) {
    asm volatile(
        "mma.sync.aligned.m16n8k8.row.col.f32.tf32.tf32.f32 "
        "{%0,%1,%2,%3}, {%4,%5,%6,%7}, {%8,%9}, {%0,%1,%2,%3};"
        : "+f"(d[0]), "+f"(d[1]), "+f"(d[2]), "+f"(d[3])
        : "r"(a0), "r"(a1), "r"(a2), "r"(a3), "r"(b0), "r"(b1));
}

// permuted fragment-friendly layout, float index of element (row, col) in a
// [128 rows x 128 k] tile: 32B per (kstep,row) group; inner order makes
// (k=tig, k=tig+4) an adjacent 8B pair -> lds.64 per fragment half.
__device__ __forceinline__ uint32_t pf(int row, int col) {
    return (uint32_t)(((col >> 3) * 128 + row) * 8 + ((col & 3) << 1) + ((col >> 2) & 1));
}

// cp.async 16B weight copy, one commit group per call
__device__ __forceinline__ void cpw(char* smB, const uint32_t* __restrict__ img, int tid) {
    uint32_t dst = (uint32_t)__cvta_generic_to_shared(smB);
    for (int i = tid; i < 4096; i += 256)
        asm volatile("cp.async.cg.shared.global [%0], [%1], 16;"
                     :: "r"(dst + (uint32_t)i * 16u), "l"(img + (size_t)i * 4) : "memory");
    asm volatile("cp.async.commit_group;" ::: "memory");
}
#define CP_WAIT0() asm volatile("cp.async.wait_group 0;" ::: "memory")

// stage global fp32 row-major tile -> smem tf32 perm layout (zero-fill OOB rows)
__device__ __forceinline__ void stageA(char* smA, const float* __restrict__ src,
                                       int m0, int limit, int tid) {
    uint32_t* a = (uint32_t*)smA;
    for (int i = tid; i < 4096; i += 256) {
        int row = i >> 5, c = (i & 31) << 2;
        float4 v = make_float4(0.f, 0.f, 0.f, 0.f);
        if (m0 + row < limit)
            v = __ldg((const float4*)(src + (size_t)(m0 + row) * 128 + c));
        a[pf(row, c + 0)] = f2tf(v.x);
        a[pf(row, c + 1)] = f2tf(v.y);
        a[pf(row, c + 2)] = f2tf(v.z);
        a[pf(row, c + 3)] = f2tf(v.w);
    }
}

// 128x128x128 warp-mma GEMM; warp covers rows [wr,wr+32) x cols [wcol,wcol+64)
__device__ __forceinline__ void gemm128(const char* smA, const char* smB,
                                        int wr, int wcol, int g, int tig,
                                        float acc[2][8][4]) {
#pragma unroll 4
    for (int ks = 0; ks < 16; ks++) {
        const char* ab = smA + ks * 4096;
        uint2 a0 = *(const uint2*)(ab + (wr + g) * 32 + tig * 8);
        uint2 a1 = *(const uint2*)(ab + (wr + g + 8) * 32 + tig * 8);
        uint2 a2 = *(const uint2*)(ab + (wr + g + 16) * 32 + tig * 8);
        uint2 a3 = *(const uint2*)(ab + (wr + g + 24) * 32 + tig * 8);
        const char* bb = smB + ks * 4096 + (wcol + g) * 32 + tig * 8;
#pragma unroll
        for (int nt = 0; nt < 8; nt++) {
            uint2 b = *(const uint2*)(bb + nt * 256);
            mma8(acc[0][nt], a0.x, a1.x, a0.y, a1.y, b.x, b.y);
            mma8(acc[1][nt], a2.x, a3.x, a2.y, a3.y, b.x, b.y);
        }
    }
}

__device__ __forceinline__ void zacc(float acc[2][8][4]) {
#pragma unroll
    for (int r = 0; r < 2; r++)
#pragma unroll
        for (int n = 0; n < 8; n++)
#pragma unroll
            for (int j = 0; j < 4; j++) acc[r][n][j] = 0.f;
}

#define SM_B0 65536
#define SM_B1 131072
#define SMEM_TOTAL 196608

// ---------------- prep: W[k][n] -> perm tf32 image [n][k] ----------------
__global__ void prep_kernel(const float* __restrict__ We1, const float* __restrict__ We2,
                            const float* __restrict__ We3, const float* __restrict__ Wn1,
                            const float* __restrict__ Wn2, const float* __restrict__ Wn3) {
    int b = blockIdx.x;
    const float* src =
        b == 0 ? We1 : b == 1 ? We1 + 16384 : b == 2 ? We1 + 32768 :
        b == 3 ? We2 : b == 4 ? We3 :
        b == 5 ? Wn1 : b == 6 ? Wn1 + 16384 :
        b == 7 ? Wn2 : Wn3;
    uint32_t* dst = g_wimg[b];
    for (int idx = threadIdx.x; idx < 16384; idx += blockDim.x) {
        int k = idx >> 7, n = idx & 127;
        dst[pf(n, k)] = f2tf(__ldg(src + k * 128 + n));
    }
}

// ---------------- proj: Ps = X@W0, Pr = X@W1; zero g_agg ----------------
__global__ void __launch_bounds__(256, 1)
proj_kernel(const float* __restrict__ X) {
    extern __shared__ char sm[];
    const int tid = threadIdx.x, lane = tid & 31, w = tid >> 5;
    const int g = lane >> 2, tig = lane & 3;
    const int wr = (w & 3) * 32, wcol = (w >> 2) * 64;
    const int m0 = blockIdx.x * 128;

    {   // zero agg
        float4* a = (float4*)g_agg;
        for (int i = blockIdx.x * 256 + tid; i < (NN * 128) / 4; i += gridDim.x * 256)
            a[i] = make_float4(0.f, 0.f, 0.f, 0.f);
    }

    cpw(sm + SM_B0, g_wimg[0], tid);
    stageA(sm, X, m0, NN, tid);
    CP_WAIT0(); __syncthreads();
    cpw(sm + SM_B1, g_wimg[1], tid);

    const int rloc[4] = {wr + g, wr + g + 8, wr + g + 16, wr + g + 24};
    float acc[2][8][4];

    zacc(acc);
    gemm128(sm, sm + SM_B0, wr, wcol, g, tig, acc);
#pragma unroll
    for (int nt = 0; nt < 8; nt++) {
        int c = wcol + nt * 8 + tig * 2;
#pragma unroll
        for (int q = 0; q < 4; q++) {
            int node = m0 + rloc[q];
            if (node < NN)
                *(float2*)(g_Ps + (size_t)node * 128 + c) =
                    make_float2(acc[q >> 1][nt][(q & 1) * 2], acc[q >> 1][nt][(q & 1) * 2 + 1]);
        }
    }

    CP_WAIT0(); __syncthreads();
    zacc(acc);
    gemm128(sm, sm + SM_B1, wr, wcol, g, tig, acc);
#pragma unroll
    for (int nt = 0; nt < 8; nt++) {
        int c = wcol + nt * 8 + tig * 2;
#pragma unroll
        for (int q = 0; q < 4; q++) {
            int node = m0 + rloc[q];
            if (node < NN)
                *(float2*)(g_Pr + (size_t)node * 128 + c) =
                    make_float2(acc[q >> 1][nt][(q & 1) * 2], acc[q >> 1][nt][(q & 1) * 2 + 1]);
        }
    }
}

// ---------------- edge: fused 3-layer MLP + gathers + scatter ----------------
__global__ void __launch_bounds__(256, 1)
edge_kernel(const float* __restrict__ EF,
            const int* __restrict__ senders, const int* __restrict__ receivers,
            const float* __restrict__ be1, const float* __restrict__ be2,
            const float* __restrict__ be3, float* __restrict__ out_edges) {
    extern __shared__ char sm[];
    const int tid = threadIdx.x, lane = tid & 31, w = tid >> 5;
    const int g = lane >> 2, tig = lane & 3;
    const int wr = (w & 3) * 32, wcol = (w >> 2) * 64;
    const int m0 = blockIdx.x * 128;
    uint32_t* smA32 = (uint32_t*)sm;

    cpw(sm + SM_B0, g_wimg[2], tid);       // We1[256:384]
    stageA(sm, EF, m0, NE, tid);
    CP_WAIT0(); __syncthreads();
    cpw(sm + SM_B1, g_wimg[3], tid);       // We2 (overlaps gemm1)

    const int rloc[4] = {wr + g, wr + g + 8, wr + g + 16, wr + g + 24};
    int ss[4], rr[4];
#pragma unroll
    for (int q = 0; q < 4; q++) {
        int e = m0 + rloc[q];
        int ec = e < NE ? e : NE - 1;
        ss[q] = __ldg(senders + ec);
        rr[q] = __ldg(receivers + ec);
    }

    float acc[2][8][4];
    zacc(acc);
    gemm128(sm, sm + SM_B0, wr, wcol, g, tig, acc);
    __syncthreads();   // everyone done reading A before rewrite

    // layer-1 epilogue: h1 = relu(D + Ps[s] + Pr[r] + be1) -> A (perm)
#pragma unroll
    for (int nt = 0; nt < 8; nt++) {
        int c = wcol + nt * 8 + tig * 2;
        float2 bi = __ldg((const float2*)(be1 + c));
#pragma unroll
        for (int q = 0; q < 4; q++) {
            float2 ps = __ldg((const float2*)(g_Ps + (size_t)ss[q] * 128 + c));
            float2 pr = __ldg((const float2*)(g_Pr + (size_t)rr[q] * 128 + c));
            float x = fmaxf(acc[q >> 1][nt][(q & 1) * 2 + 0] + ps.x + pr.x + bi.x, 0.f);
            float y = fmaxf(acc[q >> 1][nt][(q & 1) * 2 + 1] + ps.y + pr.y + bi.y, 0.f);
            smA32[pf(rloc[q], c)]     = f2tf(x);
            smA32[pf(rloc[q], c + 1)] = f2tf(y);
        }
    }
    CP_WAIT0(); __syncthreads();           // We2 ready, h1 staged
    cpw(sm + SM_B0, g_wimg[4], tid);       // We3 (overlaps gemm2)

    zacc(acc);
    gemm128(sm, sm + SM_B1, wr, wcol, g, tig, acc);
    __syncthreads();

    // layer-2 epilogue: h2 = relu(D + be2) -> A
#pragma unroll
    for (int nt = 0; nt < 8; nt++) {
        int c = wcol + nt * 8 + tig * 2;
        float2 bi = __ldg((const float2*)(be2 + c));
#pragma unroll
        for (int q = 0; q < 4; q++) {
            float x = fmaxf(acc[q >> 1][nt][(q & 1) * 2 + 0] + bi.x, 0.f);
            float y = fmaxf(acc[q >> 1][nt][(q & 1) * 2 + 1] + bi.y, 0.f);
            smA32[pf(rloc[q], c)]     = f2tf(x);
            smA32[pf(rloc[q], c + 1)] = f2tf(y);
        }
    }
    CP_WAIT0(); __syncthreads();

    zacc(acc);
    gemm128(sm, sm + SM_B0, wr, wcol, g, tig, acc);

    // layer-3 epilogue: u = D + be3; out = u + EF; agg[r] += u
#pragma unroll
    for (int nt = 0; nt < 8; nt++) {
        int c = wcol + nt * 8 + tig * 2;
        float2 bi = __ldg((const float2*)(be3 + c));
#pragma unroll
        for (int q = 0; q < 4; q++) {
            int e = m0 + rloc[q];
            if (e < NE) {
                float u0 = acc[q >> 1][nt][(q & 1) * 2 + 0] + bi.x;
                float u1 = acc[q >> 1][nt][(q & 1) * 2 + 1] + bi.y;
                float2 ef = __ldg((const float2*)(EF + (size_t)e * 128 + c));
                *(float2*)(out_edges + (size_t)e * 128 + c) =
                    make_float2(u0 + ef.x, u1 + ef.y);
                float* ag = g_agg + (size_t)rr[q] * 128 + c;
                atomicAdd(ag + 0, u0);
                atomicAdd(ag + 1, u1);
            }
        }
    }
}

// ---------------- node: fused 3-layer MLP (2-part layer 1) ----------------
__global__ void __launch_bounds__(256, 1)
node_kernel(const float* __restrict__ X,
            const float* __restrict__ bn1, const float* __restrict__ bn2,
            const float* __restrict__ bn3, float* __restrict__ out_nodes) {
    extern __shared__ char sm[];
    const int tid = threadIdx.x, lane = tid & 31, w = tid >> 5;
    const int g = lane >> 2, tig = lane & 3;
    const int wr = (w & 3) * 32, wcol = (w >> 2) * 64;
    const int m0 = blockIdx.x * 128;
    uint32_t* smA32 = (uint32_t*)sm;

    cpw(sm + SM_B0, g_wimg[5], tid);       // Wn1a
    stageA(sm, X, m0, NN, tid);
    CP_WAIT0(); __syncthreads();
    cpw(sm + SM_B1, g_wimg[6], tid);       // Wn1b

    const int rloc[4] = {wr + g, wr + g + 8, wr + g + 16, wr + g + 24};
    float acc[2][8][4];

    zacc(acc);
    gemm128(sm, sm + SM_B0, wr, wcol, g, tig, acc);   // X @ Wn1a
    __syncthreads();
    stageA(sm, g_agg, m0, NN, tid);                   // swap A -> agg
    CP_WAIT0(); __syncthreads();
    cpw(sm + SM_B0, g_wimg[7], tid);                  // Wn2
    gemm128(sm, sm + SM_B1, wr, wcol, g, tig, acc);   // + agg @ Wn1b
    __syncthreads();

    // layer-1 epilogue
#pragma unroll
    for (int nt = 0; nt < 8; nt++) {
        int c = wcol + nt * 8 + tig * 2;
        float2 bi = __ldg((const float2*)(bn1 + c));
#pragma unroll
        for (int q = 0; q < 4; q++) {
            float x = fmaxf(acc[q >> 1][nt][(q & 1) * 2 + 0] + bi.x, 0.f);
            float y = fmaxf(acc[q >> 1][nt][(q & 1) * 2 + 1] + bi.y, 0.f);
            smA32[pf(rloc[q], c)]     = f2tf(x);
            smA32[pf(rloc[q], c + 1)] = f2tf(y);
        }
    }
    CP_WAIT0(); __syncthreads();
    cpw(sm + SM_B1, g_wimg[8], tid);                  // Wn3

    zacc(acc);
    gemm128(sm, sm + SM_B0, wr, wcol, g, tig, acc);
    __syncthreads();

    // layer-2 epilogue
#pragma unroll
    for (int nt = 0; nt < 8; nt++) {
        int c = wcol + nt * 8 + tig * 2;
        float2 bi = __ldg((const float2*)(bn2 + c));
#pragma unroll
        for (int q = 0; q < 4; q++) {
            float x = fmaxf(acc[q >> 1][nt][(q & 1) * 2 + 0] + bi.x, 0.f);
            float y = fmaxf(acc[q >> 1][nt][(q & 1) * 2 + 1] + bi.y, 0.f);
            smA32[pf(rloc[q], c)]     = f2tf(x);
            smA32[pf(rloc[q], c + 1)] = f2tf(y);
        }
    }
    CP_WAIT0(); __syncthreads();

    zacc(acc);
    gemm128(sm, sm + SM_B1, wr, wcol, g, tig, acc);

    // layer-3 epilogue: out = D + bn3 + X
#pragma unroll
    for (int nt = 0; nt < 8; nt++) {
        int c = wcol + nt * 8 + tig * 2;
        float2 bi = __ldg((const float2*)(bn3 + c));
#pragma unroll
        for (int q = 0; q < 4; q++) {
            int node = m0 + rloc[q];
            if (node < NN) {
                float2 xv = __ldg((const float2*)(X + (size_t)node * 128 + c));
                *(float2*)(out_nodes + (size_t)node * 128 + c) =
                    make_float2(acc[q >> 1][nt][(q & 1) * 2 + 0] + bi.x + xv.x,
                                acc[q >> 1][nt][(q & 1) * 2 + 1] + bi.y + xv.y);
            }
        }
    }
}

// ---------------------------------------------------------------------------
extern "C" void kernel_launch(void* const* d_in, const int* in_sizes, int n_in,
                              void* d_out, int out_size) {
    const float* X   = (const float*)d_in[0];
    const float* EF  = (const float*)d_in[1];
    const int* senders   = (const int*)d_in[2];
    const int* receivers = (const int*)d_in[3];
    const float* We1 = (const float*)d_in[4];
    const float* be1 = (const float*)d_in[5];
    const float* We2 = (const float*)d_in[6];
    const float* be2 = (const float*)d_in[7];
    const float* We3 = (const float*)d_in[8];
    const float* be3 = (const float*)d_in[9];
    const float* Wn1 = (const float*)d_in[10];
    const float* bn1 = (const float*)d_in[11];
    const float* Wn2 = (const float*)d_in[12];
    const float* bn2 = (const float*)d_in[13];
    const float* Wn3 = (const float*)d_in[14];
    const float* bn3 = (const float*)d_in[15];

    float* out_nodes = (float*)d_out;
    float* out_edges = (float*)d_out + (size_t)NN * 128;

    static bool attr_done = false;
    if (!attr_done) {
        cudaFuncSetAttribute(proj_kernel, cudaFuncAttributeMaxDynamicSharedMemorySize, SMEM_TOTAL);
        cudaFuncSetAttribute(edge_kernel, cudaFuncAttributeMaxDynamicSharedMemorySize, SMEM_TOTAL);
        cudaFuncSetAttribute(node_kernel, cudaFuncAttributeMaxDynamicSharedMemorySize, SMEM_TOTAL);
        attr_done = true;
    }

    prep_kernel<<<9, 256>>>(We1, We2, We3, Wn1, Wn2, Wn3);
    proj_kernel<<<782, 256, SMEM_TOTAL>>>(X);
    edge_kernel<<<4688, 256, SMEM_TOTAL>>>(EF, senders, receivers,
                                           be1, be2, be3, out_edges);
    node_kernel<<<782, 256, SMEM_TOTAL>>>(X, bn1, bn2, bn3, out_nodes);
}